// round 1
// baseline (speedup 1.0000x reference)
#include <cuda_runtime.h>
#include <math.h>

#define NB 32
#define NA 32768
#define NG 64
#define NC 91
#define IOU_T 0.45f
#define CLIPV 4.135166556742356f /* log(1000/16) */

// ---------------- scratch (static device globals; no runtime allocation) ----------------
__device__ int                 g_matched[NB * NA];
__device__ unsigned long long  g_best_gt[NB * NG];
__device__ unsigned            g_negkey[NB * NA];
__device__ int                 g_fgcnt[NB];
__device__ double              g_bbox_sum;
__device__ double              g_fgcls_sum;
__device__ double              g_neg_sum;

// ---------------- K0: zero accumulators (runs every replay) ----------------
__global__ void k_init() {
    int t = threadIdx.x;
    for (int i = t; i < NB * NG; i += blockDim.x) g_best_gt[i] = 0ull;
    if (t < NB) g_fgcnt[t] = 0;
    if (t == 0) { g_bbox_sum = 0.0; g_fgcls_sum = 0.0; g_neg_sum = 0.0; }
}

// ---------------- K1: IoU + per-anchor argmax (matched) + per-gt argmax ----------------
// grid: (NA/1024, NB), block: 256 threads, 4 anchors per thread
__global__ void k_match(const float4* __restrict__ anchors, const float4* __restrict__ gt) {
    __shared__ float4 sgt[NG];
    __shared__ float  sga[NG];
    __shared__ unsigned long long sbest[NG];
    const int b = blockIdx.y;
    const int t = threadIdx.x;
    if (t < NG) {
        float4 g = gt[b * NG + t];
        sgt[t] = g;
        sga[t] = (g.z - g.x) * (g.w - g.y);
        sbest[t] = 0ull;
    }
    __syncthreads();

    const int a0 = blockIdx.x * 1024 + t;   // anchors: a0, a0+256, a0+512, a0+768
    float4 ab[4]; float aar[4]; float bv[4]; int bg[4];
#pragma unroll
    for (int j = 0; j < 4; j++) {
        ab[j] = anchors[(size_t)b * NA + a0 + j * 256];
        aar[j] = (ab[j].z - ab[j].x) * (ab[j].w - ab[j].y);
        bv[j] = -1.0f; bg[j] = 0;
    }

    for (int g = 0; g < NG; g++) {
        const float4 gb = sgt[g];
        const float  ga = sga[g];
        unsigned long long loc = 0ull;
#pragma unroll
        for (int j = 0; j < 4; j++) {
            float w = fminf(gb.z, ab[j].z) - fmaxf(gb.x, ab[j].x);
            float h = fminf(gb.w, ab[j].w) - fmaxf(gb.y, ab[j].y);
            w = fmaxf(w, 0.0f); h = fmaxf(h, 0.0f);
            float inter = w * h;
            float iou = inter / (ga + aar[j] - inter + 1e-16f);
            if (iou > bv[j]) { bv[j] = iou; bg[j] = g; }   // first (lowest) g wins ties
            unsigned long long p =
                ((unsigned long long)__float_as_uint(iou) << 32) |
                (unsigned long long)(0xFFFFFFFFu - (unsigned)(a0 + j * 256)); // lowest a wins ties
            loc = (p > loc) ? p : loc;
        }
#pragma unroll
        for (int off = 16; off; off >>= 1) {
            unsigned long long o = __shfl_xor_sync(0xFFFFFFFFu, loc, off);
            loc = (o > loc) ? o : loc;
        }
        if ((t & 31) == 0) atomicMax(&sbest[g], loc);
    }
    __syncthreads();
    if (t < NG) atomicMax(&g_best_gt[b * NG + t], sbest[t]);
#pragma unroll
    for (int j = 0; j < 4; j++)
        g_matched[(size_t)b * NA + a0 + j * 256] = (bv[j] < IOU_T) ? -1 : bg[j];
}

// ---------------- K2: scatter override: matched[best_anchor[g]] = g (last g wins) ------
__global__ void k_override() {
    int b = threadIdx.x;
    if (b < NB) {
        for (int g = 0; g < NG; g++) {
            unsigned long long v = g_best_gt[b * NG + g];
            unsigned a = 0xFFFFFFFFu - (unsigned)(v & 0xFFFFFFFFull);
            g_matched[(size_t)b * NA + a] = g;
        }
    }
}

// ---------------- K3a: classification loss (warp per anchor) ----------------
// grid: NB*NA/8 blocks of 256 threads
__global__ void k_cls(const float* __restrict__ logits, const int* __restrict__ labels) {
    const int wip  = threadIdx.x >> 5;
    const int lane = threadIdx.x & 31;
    const long long gw = (long long)blockIdx.x * (blockDim.x >> 5) + wip; // anchor id in [0, NB*NA)
    const int b = (int)(gw >> 15); // NA = 2^15

    const float* p = logits + gw * NC;
    float x0 = p[lane];
    float x1 = p[lane + 32];
    float x2 = (lane < NC - 64) ? p[lane + 64] : -1e30f;

    float m = fmaxf(fmaxf(x0, x1), x2);
#pragma unroll
    for (int off = 16; off; off >>= 1) m = fmaxf(m, __shfl_xor_sync(0xFFFFFFFFu, m, off));
    float s = expf(x0 - m) + expf(x1 - m) + expf(x2 - m);
#pragma unroll
    for (int off = 16; off; off >>= 1) s += __shfl_xor_sync(0xFFFFFFFFu, s, off);
    const float lse = m + logf(s);

    const int matched = g_matched[gw];
    const bool fg = (matched >= 0);
    const int idx = fg ? matched : 0;
    const int tt = fg ? labels[b * NG + idx] : (NC - 1);

    const int slot = tt >> 5, src = tt & 31;
    float cand = (slot == 0) ? x0 : ((slot == 1) ? x1 : x2);
    float xt = __shfl_sync(0xFFFFFFFFu, cand, src);
    float closs = fmaxf(lse - xt, 0.0f);

    if (lane == 0) {
        g_negkey[gw] = fg ? 0u : __float_as_uint(closs);
        if (fg) {
            atomicAdd(&g_fgcls_sum, (double)closs);
            atomicAdd(&g_fgcnt[b], 1);
        }
    }
}

// ---------------- K3b: bbox decode + GIoU loss over fg anchors ----------------
__global__ void k_bbox(const float4* __restrict__ reg,
                       const float4* __restrict__ anchors,
                       const float4* __restrict__ gt) {
    const long long i = (long long)blockIdx.x * blockDim.x + threadIdx.x;
    const int matched = g_matched[i];
    if (matched < 0) return;
    const int b = (int)(i >> 15);

    float4 a  = anchors[i];
    float4 r  = reg[i];
    float4 gb = gt[b * NG + matched];

    float w = a.z - a.x, h = a.w - a.y;
    float cx = a.x + 0.5f * w, cy = a.y + 0.5f * h;
    float dw = fminf(r.z, CLIPV), dh = fminf(r.w, CLIPV);
    float pcx = r.x * w + cx, pcy = r.y * h + cy;
    float pw = expf(dw) * w, ph = expf(dh) * h;
    float px0 = pcx - 0.5f * pw, py0 = pcy - 0.5f * ph;
    float px1 = pcx + 0.5f * pw, py1 = pcy + 0.5f * ph;

    float iw = fmaxf(fminf(px1, gb.z) - fmaxf(px0, gb.x), 0.0f);
    float ih = fmaxf(fminf(py1, gb.w) - fmaxf(py0, gb.y), 0.0f);
    float inter = iw * ih;
    float ap = (px1 - px0) * (py1 - py0);
    float ag = (gb.z - gb.x) * (gb.w - gb.y);
    float un = ap + ag - inter + 1e-16f;
    float iou = inter / un;
    float cw = fmaxf(px1, gb.z) - fminf(px0, gb.x);
    float ch = fmaxf(py1, gb.w) - fminf(py0, gb.y);
    float ac = cw * ch;
    float giou = iou - (ac - un) / fmaxf(ac, 1e-16f);
    float loss = 1.0f - fminf(fmaxf(giou, -1.0f), 1.0f);
    atomicAdd(&g_bbox_sum, (double)loss);
}

// ---------------- K4: per-batch radix-select + sum of top-K negative losses ----------------
// grid: NB blocks, 256 threads
__global__ void k_select() {
    const int b = blockIdx.x;
    const int t = threadIdx.x;
    int K = 3 * g_fgcnt[b];
    if (K <= 0) return;
    if (K > NA) K = NA;
    const unsigned* keys = g_negkey + (size_t)b * NA;

    __shared__ unsigned hist[256];
    __shared__ unsigned s_prefix;
    __shared__ int s_k;

    unsigned prefix = 0;
    int k = K;
    for (int byte = 3; byte >= 0; --byte) {
        const int sh = byte * 8;
        const unsigned mask = (byte == 3) ? 0u : (0xFFFFFFFFu << (sh + 8));
        hist[t] = 0;
        __syncthreads();
        for (int i = t; i < NA; i += 256) {
            unsigned key = keys[i];
            if ((key & mask) == prefix) atomicAdd(&hist[(key >> sh) & 255], 1u);
        }
        __syncthreads();
        if (t == 0) {
            int cum = 0;
            int v;
            s_prefix = prefix; s_k = 0;
            for (v = 255; v >= 0; --v) {
                int c = (int)hist[v];
                if (cum + c >= k) {
                    s_prefix = prefix | ((unsigned)v << sh);
                    s_k = k - cum;
                    break;
                }
                cum += c;
            }
        }
        __syncthreads();
        prefix = s_prefix;
        k = s_k;
        __syncthreads();
    }

    // sum keys strictly above threshold + k ties at threshold
    const float T = __uint_as_float(prefix);
    double local = 0.0;
    for (int i = t; i < NA; i += 256) {
        unsigned key = keys[i];
        if (key > prefix) local += (double)__uint_as_float(key);
    }
    __shared__ double ssum[256];
    ssum[t] = local;
    __syncthreads();
    for (int off = 128; off; off >>= 1) {
        if (t < off) ssum[t] += ssum[t + off];
        __syncthreads();
    }
    if (t == 0) atomicAdd(&g_neg_sum, ssum[0] + (double)k * (double)T);
}

// ---------------- K5: finalize ----------------
__global__ void k_final(float* __restrict__ out) {
    int tot = 0;
    for (int b = 0; b < NB; b++) tot += g_fgcnt[b];
    double N = (double)(tot > 1 ? tot : 1);
    out[0] = (float)(2.0 * g_bbox_sum / N);
    out[1] = (float)((g_fgcls_sum + g_neg_sum) / N);
}

// ---------------- launch ----------------
extern "C" void kernel_launch(void* const* d_in, const int* in_sizes, int n_in,
                              void* d_out, int out_size) {
    const float* cls_logits = (const float*)d_in[0];
    const float4* bbox_reg  = (const float4*)d_in[1];
    const float4* anchors   = (const float4*)d_in[2];
    const float4* gt_boxes  = (const float4*)d_in[3];
    const int*    gt_labels = (const int*)d_in[4];
    float* out = (float*)d_out;

    k_init<<<1, 256>>>();
    k_match<<<dim3(NA / 1024, NB), 256>>>(anchors, gt_boxes);
    k_override<<<1, 32>>>();
    k_cls<<<(NB * NA) / 8, 256>>>(cls_logits, gt_labels);
    k_bbox<<<(NB * NA) / 256, 256>>>(bbox_reg, anchors, gt_boxes);
    k_select<<<NB, 256>>>();
    k_final<<<1, 1>>>(out);
}

// round 3
// speedup vs baseline: 1.3310x; 1.3310x over previous
#include <cuda_runtime.h>
#include <math.h>

#define NB 32
#define NA 32768
#define NG 64
#define NC 91
#define IOU_T 0.45f
#define CLIPV 4.135166556742356f /* log(1000/16) */
#define CA 128                   /* anchors per k_cls block */

// ---------------- scratch (static device globals; no runtime allocation) ----------------
__device__ int                 g_matched[NB * NA];
__device__ unsigned long long  g_best_gt[NB * NG];
__device__ unsigned            g_negkey[NB * NA];
__device__ int                 g_fgcnt[NB];
__device__ double              g_bbox_sum;
__device__ double              g_fgcls_sum;
__device__ double              g_neg_sum;

// ---------------- K0: zero accumulators (runs every replay) ----------------
__global__ void k_init() {
    int t = threadIdx.x;
    for (int i = t; i < NB * NG; i += blockDim.x) g_best_gt[i] = 0ull;
    if (t < NB) g_fgcnt[t] = 0;
    if (t == 0) { g_bbox_sum = 0.0; g_fgcls_sum = 0.0; g_neg_sum = 0.0; }
}

// ---------------- K1: IoU + per-anchor argmax + per-gt argmax (rotation trick) ----------
// grid: (NA/1024, NB), block 256 threads, 4 anchors/thread.
// Per 32-g chunk: lane l computes g=(l+i)&31 at step i, forwards candidate to the
// owner lane with ONE shfl per step (instead of a full 5-step u64 reduce per g).
__global__ void k_match(const float4* __restrict__ anchors, const float4* __restrict__ gt) {
    __shared__ float sx0[NG], sy0[NG], sx1[NG], sy1[NG], sga[NG];
    __shared__ unsigned long long sbest[NG];
    const int b = blockIdx.y;
    const int t = threadIdx.x;
    const int lane = t & 31;
    if (t < NG) {
        float4 g = gt[b * NG + t];
        sx0[t] = g.x; sy0[t] = g.y; sx1[t] = g.z; sy1[t] = g.w;
        sga[t] = (g.z - g.x) * (g.w - g.y);
        sbest[t] = 0ull;
    }
    __syncthreads();

    const int a0 = blockIdx.x * 1024 + t;  // anchors: a0, a0+256, a0+512, a0+768
    float4 ab[4]; float aar[4]; unsigned long long bestA[4];
#pragma unroll
    for (int j = 0; j < 4; j++) {
        ab[j] = anchors[(size_t)b * NA + a0 + j * 256];
        aar[j] = (ab[j].z - ab[j].x) * (ab[j].w - ab[j].y);
        bestA[j] = 0ull;
    }

#pragma unroll
    for (int c = 0; c < 2; c++) {
        const int base = c * 32;
        unsigned long long acc = 0ull;   // per-gt best for g = base + lane
        for (int i = 0; i < 32; i++) {
            const int g = base + ((lane + i) & 31);
            const float gx0 = sx0[g], gy0 = sy0[g], gx1 = sx1[g], gy1 = sy1[g], ga = sga[g];
            unsigned long long cand = 0ull;
#pragma unroll
            for (int j = 0; j < 4; j++) {
                float w = fminf(gx1, ab[j].z) - fmaxf(gx0, ab[j].x);
                float h = fminf(gy1, ab[j].w) - fmaxf(gy0, ab[j].y);
                w = fmaxf(w, 0.0f); h = fmaxf(h, 0.0f);
                float inter = w * h;
                float iou = inter / (ga + aar[j] - inter + 1e-16f);  // exact IEEE div
                unsigned ib = __float_as_uint(iou);
                // per-gt: lowest anchor index wins ties
                unsigned long long pa =
                    ((unsigned long long)ib << 32) |
                    (unsigned long long)(0xFFFFFFFFu - (unsigned)(a0 + j * 256));
                cand = (pa > cand) ? pa : cand;
                // per-anchor: lowest g wins ties
                unsigned long long pg =
                    ((unsigned long long)ib << 32) | (unsigned)(255 - g);
                bestA[j] = (pg > bestA[j]) ? pg : bestA[j];
            }
            // owner lane o=(l+i)&31 gathers from lane (o-i)&31
            unsigned long long recv = __shfl_sync(0xFFFFFFFFu, cand, (lane - i) & 31);
            acc = (recv > acc) ? recv : acc;
        }
        atomicMax(&sbest[base + lane], acc);
    }
    __syncthreads();
    if (t < NG) atomicMax(&g_best_gt[b * NG + t], sbest[t]);
#pragma unroll
    for (int j = 0; j < 4; j++) {
        float bv = __uint_as_float((unsigned)(bestA[j] >> 32));
        int g = 255 - (int)(bestA[j] & 0xFFull);
        g_matched[(size_t)b * NA + a0 + j * 256] = (bv < IOU_T) ? -1 : g;
    }
}

// ---------------- K2: scatter override: matched[best_anchor[g]] = g (last g wins) ------
__global__ void k_override() {
    int b = threadIdx.x;
    if (b < NB) {
        for (int g = 0; g < NG; g++) {
            unsigned long long v = g_best_gt[b * NG + g];
            unsigned a = 0xFFFFFFFFu - (unsigned)(v & 0xFFFFFFFFull);
            g_matched[(size_t)b * NA + a] = g;
        }
    }
}

// ---------------- K3a: classification loss (thread per anchor, smem-staged tile) -------
// grid: NB*NA/CA blocks of CA threads. smem tile = CA*91*4 = 46592 B (static, <48KB).
__global__ void k_cls(const float* __restrict__ logits, const int* __restrict__ labels) {
    __shared__ float s[CA * NC];
    __shared__ float wsum[CA / 32];
    __shared__ int   wcnt[CA / 32];
    const int t = threadIdx.x;
    const long long a0 = (long long)blockIdx.x * CA;
    const int b = (int)(a0 >> 15);  // NA = 2^15

    // coalesced float4 staging: CA*91/4 = 2912 float4, base is 16B-aligned
    const float4* src = (const float4*)(logits + a0 * NC);
    float4* dst = (float4*)s;
    for (int i = t; i < CA * NC / 4; i += CA) dst[i] = src[i];
    __syncthreads();

    const long long gw = a0 + t;
    const int matched = g_matched[gw];
    const bool fg = (matched >= 0);
    const int tt = fg ? labels[b * NG + matched] : (NC - 1);

    // stride-91 smem row: gcd(91,32)=1 -> conflict-free
    const float* row = s + t * NC;
    float s0 = 0.f, s1 = 0.f, s2 = 0.f, s3 = 0.f;
#pragma unroll
    for (int i = 0; i < 88; i += 4) {
        s0 += __expf(row[i]);
        s1 += __expf(row[i + 1]);
        s2 += __expf(row[i + 2]);
        s3 += __expf(row[i + 3]);
    }
    s0 += __expf(row[88]); s1 += __expf(row[89]); s2 += __expf(row[90]);
    const float lse = __logf((s0 + s1) + (s2 + s3));
    const float xt = row[tt];
    const float closs = fmaxf(lse - xt, 0.0f);

    g_negkey[gw] = fg ? 0u : __float_as_uint(closs);

    // block-level fg reduction -> 2 atomics per block
    float v = fg ? closs : 0.0f;
    unsigned bal = __ballot_sync(0xFFFFFFFFu, fg);
#pragma unroll
    for (int off = 16; off; off >>= 1) v += __shfl_xor_sync(0xFFFFFFFFu, v, off);
    if ((t & 31) == 0) { wsum[t >> 5] = v; wcnt[t >> 5] = __popc(bal); }
    __syncthreads();
    if (t == 0) {
        float fs = 0.f; int fc = 0;
#pragma unroll
        for (int w = 0; w < CA / 32; w++) { fs += wsum[w]; fc += wcnt[w]; }
        if (fc > 0) {
            atomicAdd(&g_fgcls_sum, (double)fs);
            atomicAdd(&g_fgcnt[b], fc);
        }
    }
}

// ---------------- K3b: bbox decode + GIoU loss over fg anchors ----------------
__global__ void k_bbox(const float4* __restrict__ reg,
                       const float4* __restrict__ anchors,
                       const float4* __restrict__ gt) {
    const long long i = (long long)blockIdx.x * blockDim.x + threadIdx.x;
    const int matched = g_matched[i];
    if (matched < 0) return;
    const int b = (int)(i >> 15);

    float4 a  = anchors[i];
    float4 r  = reg[i];
    float4 gb = gt[b * NG + matched];

    float w = a.z - a.x, h = a.w - a.y;
    float cx = a.x + 0.5f * w, cy = a.y + 0.5f * h;
    float dw = fminf(r.z, CLIPV), dh = fminf(r.w, CLIPV);
    float pcx = r.x * w + cx, pcy = r.y * h + cy;
    float pw = expf(dw) * w, ph = expf(dh) * h;
    float px0 = pcx - 0.5f * pw, py0 = pcy - 0.5f * ph;
    float px1 = pcx + 0.5f * pw, py1 = pcy + 0.5f * ph;

    float iw = fmaxf(fminf(px1, gb.z) - fmaxf(px0, gb.x), 0.0f);
    float ih = fmaxf(fminf(py1, gb.w) - fmaxf(py0, gb.y), 0.0f);
    float inter = iw * ih;
    float ap = (px1 - px0) * (py1 - py0);
    float ag = (gb.z - gb.x) * (gb.w - gb.y);
    float un = ap + ag - inter + 1e-16f;
    float iou = inter / un;
    float cw = fmaxf(px1, gb.z) - fminf(px0, gb.x);
    float ch = fmaxf(py1, gb.w) - fminf(py0, gb.y);
    float ac = cw * ch;
    float giou = iou - (ac - un) / fmaxf(ac, 1e-16f);
    float loss = 1.0f - fminf(fmaxf(giou, -1.0f), 1.0f);
    atomicAdd(&g_bbox_sum, (double)loss);
}

// ---------------- K4: per-batch radix-select + sum of top-K negative losses ------------
__global__ void k_select() {
    const int b = blockIdx.x;
    const int t = threadIdx.x;
    int K = 3 * g_fgcnt[b];
    if (K <= 0) return;
    if (K > NA) K = NA;
    const unsigned* keys = g_negkey + (size_t)b * NA;

    __shared__ unsigned hist[256];
    __shared__ unsigned s_prefix;
    __shared__ int s_k;

    unsigned prefix = 0;
    int k = K;
    for (int byte = 3; byte >= 0; --byte) {
        const int sh = byte * 8;
        const unsigned mask = (byte == 3) ? 0u : (0xFFFFFFFFu << (sh + 8));
        hist[t] = 0;
        __syncthreads();
        for (int i = t; i < NA; i += 256) {
            unsigned key = keys[i];
            if ((key & mask) == prefix) atomicAdd(&hist[(key >> sh) & 255], 1u);
        }
        __syncthreads();
        if (t == 0) {
            int cum = 0;
            s_prefix = prefix; s_k = 0;
            for (int v = 255; v >= 0; --v) {
                int c = (int)hist[v];
                if (cum + c >= k) {
                    s_prefix = prefix | ((unsigned)v << sh);
                    s_k = k - cum;
                    break;
                }
                cum += c;
            }
        }
        __syncthreads();
        prefix = s_prefix;
        k = s_k;
        __syncthreads();
    }

    const float T = __uint_as_float(prefix);
    double local = 0.0;
    for (int i = t; i < NA; i += 256) {
        unsigned key = keys[i];
        if (key > prefix) local += (double)__uint_as_float(key);
    }
    __shared__ double ssum[256];
    ssum[t] = local;
    __syncthreads();
    for (int off = 128; off; off >>= 1) {
        if (t < off) ssum[t] += ssum[t + off];
        __syncthreads();
    }
    if (t == 0) atomicAdd(&g_neg_sum, ssum[0] + (double)k * (double)T);
}

// ---------------- K5: finalize ----------------
__global__ void k_final(float* __restrict__ out) {
    int tot = 0;
    for (int b = 0; b < NB; b++) tot += g_fgcnt[b];
    double N = (double)(tot > 1 ? tot : 1);
    out[0] = (float)(2.0 * g_bbox_sum / N);
    out[1] = (float)((g_fgcls_sum + g_neg_sum) / N);
}

// ---------------- launch ----------------
extern "C" void kernel_launch(void* const* d_in, const int* in_sizes, int n_in,
                              void* d_out, int out_size) {
    const float*  cls_logits = (const float*)d_in[0];
    const float4* bbox_reg   = (const float4*)d_in[1];
    const float4* anchors    = (const float4*)d_in[2];
    const float4* gt_boxes   = (const float4*)d_in[3];
    const int*    gt_labels  = (const int*)d_in[4];
    float* out = (float*)d_out;

    k_init<<<1, 256>>>();
    k_match<<<dim3(NA / 1024, NB), 256>>>(anchors, gt_boxes);
    k_override<<<1, 32>>>();
    k_cls<<<(NB * NA) / CA, CA>>>(cls_logits, gt_labels);
    k_bbox<<<(NB * NA) / 256, 256>>>(bbox_reg, anchors, gt_boxes);
    k_select<<<NB, 256>>>();
    k_final<<<1, 1>>>(out);
}

// round 5
// speedup vs baseline: 1.4752x; 1.1083x over previous
#include <cuda_runtime.h>
#include <math.h>

#define NB 32
#define NA 32768
#define NG 64
#define NC 91
#define RT 0.3103448275862069f  /* 0.45/1.45 : iou>=0.45  <=>  r=inter/S >= RT */
#define CLIPV 4.135166556742356f /* log(1000/16) */
#define CB 128                   /* anchors per k_cls block */
#define P0 46
#define P1 45
#define SST 47                   /* smem row stride, gcd(47,32)=1 */

// ---------------- scratch (static device globals; no runtime allocation) ----------------
__device__ int                 g_matched[NB * NA];
__device__ unsigned long long  g_best_gt[NB * NG];
__device__ unsigned            g_negkey[NB * NA];
__device__ int                 g_fgcnt[NB];
__device__ double              g_bbox_sum;
__device__ double              g_fgcls_sum;
__device__ double              g_neg_sum;

// ---------------- K0: zero accumulators (runs every replay) ----------------
__global__ void k_init() {
    int t = threadIdx.x;
    for (int i = t; i < NB * NG; i += blockDim.x) g_best_gt[i] = 0ull;
    if (t < NB) g_fgcnt[t] = 0;
    if (t == 0) { g_bbox_sum = 0.0; g_fgcls_sum = 0.0; g_neg_sum = 0.0; }
}

// ---------------- K1: IoU matching, r-transform, 8 anchors/thread ----------------
// grid: (NA/2048, NB), block 256.  r = inter/(area_g+area_a) is a monotone
// transform of IoU: same argmax, threshold maps to RT. Per-anchor argmax is a
// full-precision fp compare; per-gt argmax tracked as fp (r,j) per thread, packed
// to u64 (r||~anchor) only at the rotation-shfl boundary.
__global__ void __launch_bounds__(256) k_match(const float4* __restrict__ anchors,
                                               const float4* __restrict__ gt) {
    __shared__ float sx0[NG], sy0[NG], sx1[NG], sy1[NG], sga[NG];
    __shared__ unsigned long long sbest[NG];
    const int b = blockIdx.y;
    const int t = threadIdx.x;
    const int lane = t & 31;
    if (t < NG) {
        float4 g = gt[b * NG + t];
        sx0[t] = g.x; sy0[t] = g.y; sx1[t] = g.z; sy1[t] = g.w;
        sga[t] = (g.z - g.x) * (g.w - g.y);
        sbest[t] = 0ull;
    }
    __syncthreads();

    const int a0 = blockIdx.x * 2048 + t;  // anchors: a0 + j*256, j=0..7
    float ax0[8], ay0[8], ax1[8], ay1[8], aar[8], bv[8];
    int bg[8];
#pragma unroll
    for (int j = 0; j < 8; j++) {
        float4 a = anchors[(size_t)b * NA + a0 + j * 256];
        ax0[j] = a.x; ay0[j] = a.y; ax1[j] = a.z; ay1[j] = a.w;
        aar[j] = (a.z - a.x) * (a.w - a.y);
        bv[j] = 0.0f; bg[j] = 0;
    }

#pragma unroll
    for (int c = 0; c < 2; c++) {
        const int base = c * 32;
        unsigned long long acc = 0ull;   // per-gt best for g = base + lane
#pragma unroll 2
        for (int i = 0; i < 32; i++) {
            const int g = base + ((lane + i) & 31);
            const float gx0 = sx0[g], gy0 = sy0[g], gx1 = sx1[g], gy1 = sy1[g], ga = sga[g];
            float cr = 0.0f; int cj = 0;
#pragma unroll
            for (int j = 0; j < 8; j++) {
                float w = fminf(gx1, ax1[j]) - fmaxf(gx0, ax0[j]);
                float h = fminf(gy1, ay1[j]) - fmaxf(gy0, ay0[j]);
                w = fmaxf(w, 0.0f); h = fmaxf(h, 0.0f);
                float inter = w * h;
                float r = __fdividef(inter, ga + aar[j]);
                if (r > bv[j]) { bv[j] = r; bg[j] = g; }   // first (rotation) wins fp ties
                if (r > cr)    { cr = r;     cj = j;    }   // lowest j (lowest anchor) wins ties
            }
            unsigned long long cand =
                ((unsigned long long)__float_as_uint(cr) << 32) |
                (unsigned long long)(0xFFFFFFFFu - (unsigned)(a0 + cj * 256));
            unsigned long long recv = __shfl_sync(0xFFFFFFFFu, cand, (lane - i) & 31);
            acc = (recv > acc) ? recv : acc;
        }
        atomicMax(&sbest[base + lane], acc);
    }
    __syncthreads();
    if (t < NG) atomicMax(&g_best_gt[b * NG + t], sbest[t]);
#pragma unroll
    for (int j = 0; j < 8; j++)
        g_matched[(size_t)b * NA + a0 + j * 256] = (bv[j] < RT) ? -1 : bg[j];
}

// ---------------- K2: scatter override: matched[best_anchor[g]] = g (last g wins) ------
__global__ void k_override() {
    int b = threadIdx.x;
    if (b < NB) {
        for (int g = 0; g < NG; g++) {
            unsigned long long v = g_best_gt[b * NG + g];
            unsigned a = 0xFFFFFFFFu - (unsigned)(v & 0xFFFFFFFFull);
            g_matched[(size_t)b * NA + a] = g;
        }
    }
}

// ---------------- K3a: classification loss (two-phase smem staging) ----------------
// grid NB*NA/CB blocks of CB threads; smem 128x47 fp32 = 24KB -> ~9 blocks/SM.
__global__ void __launch_bounds__(CB) k_cls(const float* __restrict__ logits,
                                            const int* __restrict__ labels) {
    __shared__ float s[CB * SST];
    __shared__ float wsum[CB / 32];
    __shared__ int   wcnt[CB / 32];
    const int t = threadIdx.x;
    const long long a0 = (long long)blockIdx.x * CB;
    const int b = (int)(a0 >> 15);  // NA = 2^15
    const float* base = logits + a0 * NC;

    const int matched = g_matched[a0 + t];
    const bool fg = (matched >= 0);
    const int tt = fg ? labels[b * NG + matched] : (NC - 1);

    float xt = 0.0f, s0 = 0.f, s1 = 0.f, s2 = 0.f, s3 = 0.f;

    // ---- phase 0: classes [0, 46) ----
    for (int idx = t; idx < CB * P0; idx += CB) {
        int r = idx / P0, c = idx - r * P0;
        s[r * SST + c] = base[r * NC + c];
    }
    __syncthreads();
    {
        const float* row = s + t * SST;
#pragma unroll
        for (int i = 0; i < 44; i += 4) {
            s0 += __expf(row[i]);     s1 += __expf(row[i + 1]);
            s2 += __expf(row[i + 2]); s3 += __expf(row[i + 3]);
        }
        s0 += __expf(row[44]); s1 += __expf(row[45]);
        if (tt < P0) xt = row[tt];
    }
    __syncthreads();

    // ---- phase 1: classes [46, 91) ----
    for (int idx = t; idx < CB * P1; idx += CB) {
        int r = idx / P1, c = idx - r * P1;
        s[r * SST + c] = base[r * NC + P0 + c];
    }
    __syncthreads();
    {
        const float* row = s + t * SST;
#pragma unroll
        for (int i = 0; i < 44; i += 4) {
            s0 += __expf(row[i]);     s1 += __expf(row[i + 1]);
            s2 += __expf(row[i + 2]); s3 += __expf(row[i + 3]);
        }
        s0 += __expf(row[44]);
        if (tt >= P0) xt = row[tt - P0];
    }

    const float lse = __logf((s0 + s1) + (s2 + s3));
    const float closs = fmaxf(lse - xt, 0.0f);
    g_negkey[a0 + t] = fg ? 0u : __float_as_uint(closs);

    // block-level fg reduction -> 2 atomics per block
    float v = fg ? closs : 0.0f;
    unsigned bal = __ballot_sync(0xFFFFFFFFu, fg);
#pragma unroll
    for (int off = 16; off; off >>= 1) v += __shfl_xor_sync(0xFFFFFFFFu, v, off);
    if ((t & 31) == 0) { wsum[t >> 5] = v; wcnt[t >> 5] = __popc(bal); }
    __syncthreads();
    if (t == 0) {
        float fs = 0.f; int fc = 0;
#pragma unroll
        for (int w = 0; w < CB / 32; w++) { fs += wsum[w]; fc += wcnt[w]; }
        if (fc > 0) {
            atomicAdd(&g_fgcls_sum, (double)fs);
            atomicAdd(&g_fgcnt[b], fc);
        }
    }
}

// ---------------- K3b: bbox decode + GIoU loss over fg anchors ----------------
__global__ void k_bbox(const float4* __restrict__ reg,
                       const float4* __restrict__ anchors,
                       const float4* __restrict__ gt) {
    const long long i = (long long)blockIdx.x * blockDim.x + threadIdx.x;
    const int matched = g_matched[i];
    if (matched < 0) return;
    const int b = (int)(i >> 15);

    float4 a  = anchors[i];
    float4 r  = reg[i];
    float4 gb = gt[b * NG + matched];

    float w = a.z - a.x, h = a.w - a.y;
    float cx = a.x + 0.5f * w, cy = a.y + 0.5f * h;
    float dw = fminf(r.z, CLIPV), dh = fminf(r.w, CLIPV);
    float pcx = r.x * w + cx, pcy = r.y * h + cy;
    float pw = expf(dw) * w, ph = expf(dh) * h;
    float px0 = pcx - 0.5f * pw, py0 = pcy - 0.5f * ph;
    float px1 = pcx + 0.5f * pw, py1 = pcy + 0.5f * ph;

    float iw = fmaxf(fminf(px1, gb.z) - fmaxf(px0, gb.x), 0.0f);
    float ih = fmaxf(fminf(py1, gb.w) - fmaxf(py0, gb.y), 0.0f);
    float inter = iw * ih;
    float ap = (px1 - px0) * (py1 - py0);
    float ag = (gb.z - gb.x) * (gb.w - gb.y);
    float un = ap + ag - inter + 1e-16f;
    float iou = inter / un;
    float cw = fmaxf(px1, gb.z) - fminf(px0, gb.x);
    float ch = fmaxf(py1, gb.w) - fminf(py0, gb.y);
    float ac = cw * ch;
    float giou = iou - (ac - un) / fmaxf(ac, 1e-16f);
    float loss = 1.0f - fminf(fmaxf(giou, -1.0f), 1.0f);
    atomicAdd(&g_bbox_sum, (double)loss);
}

// ---------------- K4: per-batch radix-select + sum of top-K negative losses ------------
__global__ void k_select() {
    const int b = blockIdx.x;
    const int t = threadIdx.x;
    int K = 3 * g_fgcnt[b];
    if (K <= 0) return;
    if (K > NA) K = NA;
    const unsigned* keys = g_negkey + (size_t)b * NA;

    __shared__ unsigned hist[256];
    __shared__ unsigned s_prefix;
    __shared__ int s_k;

    unsigned prefix = 0;
    int k = K;
    for (int byte = 3; byte >= 0; --byte) {
        const int sh = byte * 8;
        const unsigned mask = (byte == 3) ? 0u : (0xFFFFFFFFu << (sh + 8));
        hist[t] = 0;
        __syncthreads();
        for (int i = t; i < NA; i += 256) {
            unsigned key = keys[i];
            if ((key & mask) == prefix) atomicAdd(&hist[(key >> sh) & 255], 1u);
        }
        __syncthreads();
        if (t == 0) {
            int cum = 0;
            s_prefix = prefix; s_k = 0;
            for (int v = 255; v >= 0; --v) {
                int c = (int)hist[v];
                if (cum + c >= k) {
                    s_prefix = prefix | ((unsigned)v << sh);
                    s_k = k - cum;
                    break;
                }
                cum += c;
            }
        }
        __syncthreads();
        prefix = s_prefix;
        k = s_k;
        __syncthreads();
    }

    const float T = __uint_as_float(prefix);
    double local = 0.0;
    for (int i = t; i < NA; i += 256) {
        unsigned key = keys[i];
        if (key > prefix) local += (double)__uint_as_float(key);
    }
    __shared__ double ssum[256];
    ssum[t] = local;
    __syncthreads();
    for (int off = 128; off; off >>= 1) {
        if (t < off) ssum[t] += ssum[t + off];
        __syncthreads();
    }
    if (t == 0) atomicAdd(&g_neg_sum, ssum[0] + (double)k * (double)T);
}

// ---------------- K5: finalize ----------------
__global__ void k_final(float* __restrict__ out) {
    int tot = 0;
    for (int b = 0; b < NB; b++) tot += g_fgcnt[b];
    double N = (double)(tot > 1 ? tot : 1);
    out[0] = (float)(2.0 * g_bbox_sum / N);
    out[1] = (float)((g_fgcls_sum + g_neg_sum) / N);
}

// ---------------- launch ----------------
extern "C" void kernel_launch(void* const* d_in, const int* in_sizes, int n_in,
                              void* d_out, int out_size) {
    const float*  cls_logits = (const float*)d_in[0];
    const float4* bbox_reg   = (const float4*)d_in[1];
    const float4* anchors    = (const float4*)d_in[2];
    const float4* gt_boxes   = (const float4*)d_in[3];
    const int*    gt_labels  = (const int*)d_in[4];
    float* out = (float*)d_out;

    k_init<<<1, 256>>>();
    k_match<<<dim3(NA / 2048, NB), 256>>>(anchors, gt_boxes);
    k_override<<<1, 32>>>();
    k_cls<<<(NB * NA) / CB, CB>>>(cls_logits, gt_labels);
    k_bbox<<<(NB * NA) / 256, 256>>>(bbox_reg, anchors, gt_boxes);
    k_select<<<NB, 256>>>();
    k_final<<<1, 1>>>(out);
}

// round 6
// speedup vs baseline: 2.8019x; 1.8993x over previous
#include <cuda_runtime.h>
#include <math.h>

#define NB 32
#define NA 32768
#define NG 64
#define NC 91
#define RT 0.3103448275862069f   /* 0.45/1.45 : iou>=0.45  <=>  r=inter/S >= RT */
#define CLIPV 4.135166556742356f /* log(1000/16) */
#define CB 256                   /* anchors per k_cls block */
#define CLS_SMEM (CB * NC * 4)   /* 93184 B dynamic */

// ---------------- scratch (static device globals; no runtime allocation) ----------------
__device__ int                 g_matched[NB * NA];
__device__ unsigned long long  g_best_gt[NB * NG];
__device__ unsigned            g_negkey[NB * NA];
__device__ int                 g_fgcnt[NB];
__device__ double              g_bbox_sum;
__device__ double              g_fgcls_sum;
__device__ double              g_neg_sum;

// ---------------- K0: zero accumulators (runs every replay) ----------------
__global__ void k_init() {
    int t = threadIdx.x;
    for (int i = t; i < NB * NG; i += blockDim.x) g_best_gt[i] = 0ull;
    if (t < NB) g_fgcnt[t] = 0;
    if (t == 0) { g_bbox_sum = 0.0; g_fgcls_sum = 0.0; g_neg_sum = 0.0; }
}

// ---------------- K1: IoU matching, 4 anchors/thread (high occupancy) ----------------
// grid (NA/1024, NB), block 256. r = inter/(area_g+area_a): monotone in IoU.
__global__ void __launch_bounds__(256) k_match(const float4* __restrict__ anchors,
                                               const float4* __restrict__ gt) {
    __shared__ float4 sgt[NG];
    __shared__ float  sga[NG];
    __shared__ unsigned long long sbest[NG];
    const int b = blockIdx.y;
    const int t = threadIdx.x;
    const int lane = t & 31;
    if (t < NG) {
        float4 g = gt[b * NG + t];
        sgt[t] = g;
        sga[t] = (g.z - g.x) * (g.w - g.y);
        sbest[t] = 0ull;
    }
    __syncthreads();

    const int a0 = blockIdx.x * 1024 + t;  // anchors a0 + j*256, j=0..3
    float ax0[4], ay0[4], ax1[4], ay1[4], aar[4], bv[4];
    int bg[4];
#pragma unroll
    for (int j = 0; j < 4; j++) {
        float4 a = anchors[(size_t)b * NA + a0 + j * 256];
        ax0[j] = a.x; ay0[j] = a.y; ax1[j] = a.z; ay1[j] = a.w;
        aar[j] = (a.z - a.x) * (a.w - a.y);
        bv[j] = 0.0f; bg[j] = 0;
    }

#pragma unroll
    for (int c = 0; c < 2; c++) {
        const int base = c * 32;
        unsigned long long acc = 0ull;  // per-gt best for g = base + lane
        for (int i = 0; i < 32; i++) {
            const int g = base + ((lane + i) & 31);
            const float4 gb = sgt[g];
            const float  ga = sga[g];
            float cr = 0.0f; int ca = a0;
#pragma unroll
            for (int j = 0; j < 4; j++) {
                float w = fminf(gb.z, ax1[j]) - fmaxf(gb.x, ax0[j]);
                float h = fminf(gb.w, ay1[j]) - fmaxf(gb.y, ay0[j]);
                w = fmaxf(w, 0.0f); h = fmaxf(h, 0.0f);
                float inter = w * h;
                float r = __fdividef(inter, ga + aar[j]);
                if (r > bv[j]) { bv[j] = r; bg[j] = g; }        // first g wins ties
                if (r > cr)    { cr = r; ca = a0 + j * 256; }   // lowest anchor wins ties
            }
            unsigned long long cand =
                ((unsigned long long)__float_as_uint(cr) << 32) |
                (unsigned long long)(0xFFFFFFFFu - (unsigned)ca);
            unsigned long long recv = __shfl_sync(0xFFFFFFFFu, cand, (lane - i) & 31);
            acc = (recv > acc) ? recv : acc;
        }
        atomicMax(&sbest[base + lane], acc);
    }
    __syncthreads();
    if (t < NG) atomicMax(&g_best_gt[b * NG + t], sbest[t]);
#pragma unroll
    for (int j = 0; j < 4; j++)
        g_matched[(size_t)b * NA + a0 + j * 256] = (bv[j] < RT) ? -1 : bg[j];
}

// ---------------- K2: scatter override: matched[best_anchor[g]] = g (last g wins) ------
__global__ void k_override() {
    int b = threadIdx.x;
    if (b < NB) {
#pragma unroll 8
        for (int g = 0; g < NG; g++) {
            unsigned long long v = g_best_gt[b * NG + g];
            unsigned a = 0xFFFFFFFFu - (unsigned)(v & 0xFFFFFFFFull);
            g_matched[(size_t)b * NA + a] = g;
        }
    }
}

// ---------------- K3: fused classification loss + bbox GIoU (anchor-aligned blocks) ----
// grid NB*NA/CB blocks of CB threads; dynamic smem CB*91*4 = 93184 -> 2 blocks/SM.
__global__ void __launch_bounds__(CB) k_cls(const float*  __restrict__ logits,
                                            const int*    __restrict__ labels,
                                            const float4* __restrict__ reg,
                                            const float4* __restrict__ anchors,
                                            const float4* __restrict__ gt) {
    extern __shared__ float s[];            // CB*NC floats
    __shared__ float wsum[CB / 32], wbb[CB / 32];
    __shared__ int   wcnt[CB / 32];
    const int t = threadIdx.x;
    const long long a0 = (long long)blockIdx.x * CB;
    const int b = (int)(a0 >> 15);          // NA = 2^15

    // coalesced float4 staging (a0*91 floats is 16B-aligned since a0 % 4 == 0)
    const float4* src = (const float4*)(logits + a0 * NC);
    float4* dst = (float4*)s;
    for (int i = t; i < CB * NC / 4; i += CB) dst[i] = src[i];
    __syncthreads();

    const int matched = g_matched[a0 + t];
    const bool fg = (matched >= 0);
    const int tt = fg ? labels[b * NG + matched] : (NC - 1);

    const float* row = s + t * NC;          // stride 91: gcd(91,32)=1, conflict-free
    float s0 = 0.f, s1 = 0.f, s2 = 0.f, s3 = 0.f;
#pragma unroll
    for (int i = 0; i < 88; i += 4) {
        s0 += __expf(row[i]);     s1 += __expf(row[i + 1]);
        s2 += __expf(row[i + 2]); s3 += __expf(row[i + 3]);
    }
    s0 += __expf(row[88]); s1 += __expf(row[89]); s2 += __expf(row[90]);
    const float lse = __logf((s0 + s1) + (s2 + s3));
    const float closs = fmaxf(lse - row[tt], 0.0f);
    g_negkey[a0 + t] = fg ? 0u : __float_as_uint(closs);

    // fused bbox decode + GIoU for fg anchors
    float bloss = 0.0f;
    if (fg) {
        float4 a  = anchors[a0 + t];
        float4 r  = reg[a0 + t];
        float4 gb = gt[b * NG + matched];
        float w = a.z - a.x, h = a.w - a.y;
        float cx = a.x + 0.5f * w, cy = a.y + 0.5f * h;
        float dw = fminf(r.z, CLIPV), dh = fminf(r.w, CLIPV);
        float pcx = r.x * w + cx, pcy = r.y * h + cy;
        float pw = __expf(dw) * w, ph = __expf(dh) * h;
        float px0 = pcx - 0.5f * pw, py0 = pcy - 0.5f * ph;
        float px1 = pcx + 0.5f * pw, py1 = pcy + 0.5f * ph;
        float iw = fmaxf(fminf(px1, gb.z) - fmaxf(px0, gb.x), 0.0f);
        float ih = fmaxf(fminf(py1, gb.w) - fmaxf(py0, gb.y), 0.0f);
        float inter = iw * ih;
        float ap = (px1 - px0) * (py1 - py0);
        float ag = (gb.z - gb.x) * (gb.w - gb.y);
        float un = ap + ag - inter + 1e-16f;
        float iou = inter / un;
        float cw = fmaxf(px1, gb.z) - fminf(px0, gb.x);
        float ch = fmaxf(py1, gb.w) - fminf(py0, gb.y);
        float ac = cw * ch;
        float giou = iou - (ac - un) / fmaxf(ac, 1e-16f);
        bloss = 1.0f - fminf(fmaxf(giou, -1.0f), 1.0f);
    }

    // block-level reductions -> <=3 atomics per block
    float v  = fg ? closs : 0.0f;
    float bb = bloss;
    unsigned bal = __ballot_sync(0xFFFFFFFFu, fg);
#pragma unroll
    for (int off = 16; off; off >>= 1) {
        v  += __shfl_xor_sync(0xFFFFFFFFu, v, off);
        bb += __shfl_xor_sync(0xFFFFFFFFu, bb, off);
    }
    if ((t & 31) == 0) { wsum[t >> 5] = v; wbb[t >> 5] = bb; wcnt[t >> 5] = __popc(bal); }
    __syncthreads();
    if (t == 0) {
        float fs = 0.f, fb = 0.f; int fc = 0;
#pragma unroll
        for (int w = 0; w < CB / 32; w++) { fs += wsum[w]; fb += wbb[w]; fc += wcnt[w]; }
        if (fc > 0) {
            atomicAdd(&g_fgcls_sum, (double)fs);
            atomicAdd(&g_bbox_sum, (double)fb);
            atomicAdd(&g_fgcnt[b], fc);
        }
    }
}

// ---------------- K4: per-batch radix-select + top-K sum (1024 threads) ----------------
__global__ void __launch_bounds__(1024) k_select() {
    const int b = blockIdx.x;
    const int t = threadIdx.x;
    int K = 3 * g_fgcnt[b];
    if (K <= 0) return;
    if (K > NA) K = NA;
    const unsigned* keys = g_negkey + (size_t)b * NA;

    __shared__ unsigned hist[256];
    __shared__ unsigned s_prefix;
    __shared__ int s_k;

    unsigned prefix = 0;
    int k = K;
    for (int byte = 3; byte >= 0; --byte) {
        const int sh = byte * 8;
        const unsigned mask = (byte == 3) ? 0u : (0xFFFFFFFFu << (sh + 8));
        if (t < 256) hist[t] = 0;
        __syncthreads();
#pragma unroll 4
        for (int i = t; i < NA; i += 1024) {
            unsigned key = keys[i];
            if ((key & mask) == prefix) atomicAdd(&hist[(key >> sh) & 255], 1u);
        }
        __syncthreads();
        if (t == 0) {
            int cum = 0;
            s_prefix = prefix; s_k = 0;
            for (int v = 255; v >= 0; --v) {
                int c = (int)hist[v];
                if (cum + c >= k) {
                    s_prefix = prefix | ((unsigned)v << sh);
                    s_k = k - cum;
                    break;
                }
                cum += c;
            }
        }
        __syncthreads();
        prefix = s_prefix;
        k = s_k;
        __syncthreads();
    }

    const float T = __uint_as_float(prefix);
    double local = 0.0;
#pragma unroll 4
    for (int i = t; i < NA; i += 1024) {
        unsigned key = keys[i];
        if (key > prefix) local += (double)__uint_as_float(key);
    }
    __shared__ double ssum[1024];
    ssum[t] = local;
    __syncthreads();
    for (int off = 512; off; off >>= 1) {
        if (t < off) ssum[t] += ssum[t + off];
        __syncthreads();
    }
    if (t == 0) atomicAdd(&g_neg_sum, ssum[0] + (double)k * (double)T);
}

// ---------------- K5: finalize ----------------
__global__ void k_final(float* __restrict__ out) {
    int tot = 0;
    for (int b = 0; b < NB; b++) tot += g_fgcnt[b];
    double N = (double)(tot > 1 ? tot : 1);
    out[0] = (float)(2.0 * g_bbox_sum / N);
    out[1] = (float)((g_fgcls_sum + g_neg_sum) / N);
}

// ---------------- launch ----------------
extern "C" void kernel_launch(void* const* d_in, const int* in_sizes, int n_in,
                              void* d_out, int out_size) {
    const float*  cls_logits = (const float*)d_in[0];
    const float4* bbox_reg   = (const float4*)d_in[1];
    const float4* anchors    = (const float4*)d_in[2];
    const float4* gt_boxes   = (const float4*)d_in[3];
    const int*    gt_labels  = (const int*)d_in[4];
    float* out = (float*)d_out;

    cudaFuncSetAttribute(k_cls, cudaFuncAttributeMaxDynamicSharedMemorySize, CLS_SMEM);

    k_init<<<1, 256>>>();
    k_match<<<dim3(NA / 1024, NB), 256>>>(anchors, gt_boxes);
    k_override<<<1, 32>>>();
    k_cls<<<(NB * NA) / CB, CB, CLS_SMEM>>>(cls_logits, gt_labels, bbox_reg, anchors, gt_boxes);
    k_select<<<NB, 1024>>>();
    k_final<<<1, 1>>>(out);
}